// round 5
// baseline (speedup 1.0000x reference)
#include <cuda_runtime.h>
#include <cuda_fp16.h>
#include <cstdint>

// ---------------------------------------------------------------------------
// Problem constants
// ---------------------------------------------------------------------------
#define D_IN   4096
#define D_OUT  4096
#define M_TOT  8192
#define RANK   64

// GEMM tiling (fp16 operands, fp32 accumulate)
#define TM 128
#define TN 256
#define TK 64                        // halves per K-stage = 128 bytes
#define STAGES 3
#define K_ITERS (D_IN / TK)          // 64
#define M_TILES (M_TOT / TM)         // 64
#define N_TILES (D_OUT / TN)         // 16

#define PADH 8
#define ROWH (TK + PADH)             // 72 halves = 144 B rows
#define A_STAGE_H (TM * ROWH)
#define B_STAGE_H (TN * ROWH)
#define SMEM_BYTES ((STAGES * (A_STAGE_H + B_STAGE_H)) * 2)   // 165888

// ---------------------------------------------------------------------------
// Device globals (allocation-free scratch)
// ---------------------------------------------------------------------------
__constant__ float c_nf4[16] = {
    -1.0f, -0.6962f, -0.5251f, -0.3949f, -0.2844f, -0.1848f,
    -0.0911f, 0.0f, 0.0796f, 0.1609f, 0.2461f, 0.3379f,
    0.4407f, 0.5626f, 0.723f, 1.0f};

__device__ __align__(1024) __half g_wh[(size_t)D_OUT * D_IN];
__device__ __align__(1024) __half g_xh[(size_t)M_TOT * D_IN];

// ---------------------------------------------------------------------------
// Helpers
// ---------------------------------------------------------------------------
__device__ __forceinline__ void cp_async16(uint32_t smem_addr, const void* gptr) {
    asm volatile("cp.async.cg.shared.global [%0], [%1], 16;"
                 :: "r"(smem_addr), "l"(gptr) : "memory");
}
#define CP_COMMIT() asm volatile("cp.async.commit_group;" ::: "memory")
#define CP_WAIT(n)  asm volatile("cp.async.wait_group %0;" :: "n"(n) : "memory")

#define LDMATRIX_X4(r0, r1, r2, r3, addr)                                     \
    asm volatile("ldmatrix.sync.aligned.m8n8.x4.shared.b16 {%0,%1,%2,%3}, [%4];" \
                 : "=r"(r0), "=r"(r1), "=r"(r2), "=r"(r3) : "r"(addr))

__device__ __forceinline__ void mma_f16(float* c, const uint32_t* a,
                                        uint32_t b0, uint32_t b1) {
    asm volatile(
        "mma.sync.aligned.m16n8k16.row.col.f32.f16.f16.f32 "
        "{%0,%1,%2,%3}, {%4,%5,%6,%7}, {%8,%9}, {%0,%1,%2,%3};"
        : "+f"(c[0]), "+f"(c[1]), "+f"(c[2]), "+f"(c[3])
        : "r"(a[0]), "r"(a[1]), "r"(a[2]), "r"(a[3]), "r"(b0), "r"(b1));
}

__device__ __forceinline__ uint32_t h2_bits(__half2 h) {
    return *reinterpret_cast<uint32_t*>(&h);
}

// ---------------------------------------------------------------------------
// Prep 1: convert x to fp16
// ---------------------------------------------------------------------------
__global__ __launch_bounds__(256) void convert_x_kernel(const float4* __restrict__ x,
                                                        uint2* __restrict__ xh, int n4) {
    int i = blockIdx.x * blockDim.x + threadIdx.x;
    int stride = gridDim.x * blockDim.x;
    for (; i < n4; i += stride) {
        float4 v = x[i];
        uint2 o;
        o.x = h2_bits(__floats2half2_rn(v.x, v.y));
        o.y = h2_bits(__floats2half2_rn(v.z, v.w));
        xh[i] = o;
    }
}

// ---------------------------------------------------------------------------
// Prep 2: W_eff[o,i] = NF4[q[o,i]]*scale + 0.25 * (B@A)[o,i], to fp16
// ---------------------------------------------------------------------------
__global__ __launch_bounds__(256) void prep_weff_kernel(
    const int* __restrict__ q, const float* __restrict__ wscale,
    const float* __restrict__ lA, const float* __restrict__ lB,
    uint2* __restrict__ wh) {
    __shared__ float sA[64][68];
    __shared__ float sB[64][68];
    const int tid = threadIdx.x;
    const int i0 = blockIdx.x * 64;
    const int o0 = blockIdx.y * 64;

    for (int idx = tid; idx < 64 * 64; idx += 256) {
        int r = idx >> 6, c = idx & 63;
        sA[r][c] = lA[r * D_IN + i0 + c];
    }
    for (int idx = tid; idx < 64 * 64; idx += 256) {
        int o = idx >> 6, r = idx & 63;
        sB[r][o] = lB[(size_t)(o0 + o) * RANK + r];
    }
    __syncthreads();

    const int tx = tid & 15;
    const int ty = tid >> 4;
    float acc[4][4] = {};
#pragma unroll
    for (int r = 0; r < 64; r++) {
        const float4 av = *reinterpret_cast<const float4*>(&sA[r][tx * 4]);
        const float4 bv = *reinterpret_cast<const float4*>(&sB[r][ty * 4]);
        const float a[4] = {av.x, av.y, av.z, av.w};
        const float b[4] = {bv.x, bv.y, bv.z, bv.w};
#pragma unroll
        for (int ii = 0; ii < 4; ii++)
#pragma unroll
            for (int jj = 0; jj < 4; jj++)
                acc[ii][jj] += b[ii] * a[jj];
    }

    const float s = wscale[0];
#pragma unroll
    for (int ii = 0; ii < 4; ii++) {
        const size_t o = o0 + ty * 4 + ii;
        const int4 qv = *reinterpret_cast<const int4*>(&q[o * D_IN + i0 + tx * 4]);
        float f0 = c_nf4[qv.x & 15] * s + 0.25f * acc[ii][0];
        float f1 = c_nf4[qv.y & 15] * s + 0.25f * acc[ii][1];
        float f2 = c_nf4[qv.z & 15] * s + 0.25f * acc[ii][2];
        float f3 = c_nf4[qv.w & 15] * s + 0.25f * acc[ii][3];
        uint2 o2;
        o2.x = h2_bits(__floats2half2_rn(f0, f1));
        o2.y = h2_bits(__floats2half2_rn(f2, f3));
        wh[(o * D_IN + i0 + tx * 4) >> 2] = o2;
    }
}

// ---------------------------------------------------------------------------
// Main GEMM: C[m,n] = sum_k Xh[m,k] * Wh[n,k]
// 128x256 CTA, 64x64 warp tiles, 3-stage cp.async, fragment double-buffering
// ---------------------------------------------------------------------------
__global__ void __launch_bounds__(256, 1)
gemm_f16_kernel(const __half* __restrict__ A, const __half* __restrict__ B,
                float* __restrict__ C) {
    extern __shared__ __half smem[];
    __half* As = smem;
    __half* Bs = smem + STAGES * A_STAGE_H;

    const int tid = threadIdx.x;
    const int warp = tid >> 5;
    const int lane = tid & 31;

    const int bid = blockIdx.x;
    const int GROUP_M = 8;
    const int per_group = GROUP_M * N_TILES;
    const int g = bid / per_group, rem = bid % per_group;
    const int mt = g * GROUP_M + (rem % GROUP_M);
    const int nt = rem / GROUP_M;
    const int m0 = mt * TM, n0 = nt * TN;

    const int wm = (warp & 1) * 64;
    const int wn = (warp >> 1) * 64;

    const int lrow = tid >> 3;
    const int lcolh = (tid & 7) * 8;

    const uint32_t as_base = (uint32_t)__cvta_generic_to_shared(As);
    const uint32_t bs_base = (uint32_t)__cvta_generic_to_shared(Bs);

    auto load_stage = [&](int kt, int s) {
        const int k0 = kt * TK;
        const __half* ga = A + (size_t)m0 * D_IN + k0 + lcolh;
        const __half* gb = B + (size_t)n0 * D_IN + k0 + lcolh;
        uint32_t sa = as_base + (s * A_STAGE_H + lcolh) * 2;
        uint32_t sb = bs_base + (s * B_STAGE_H + lcolh) * 2;
#pragma unroll
        for (int it = 0; it < 4; it++) {
            int row = lrow + it * 32;
            cp_async16(sa + row * (ROWH * 2), ga + (size_t)row * D_IN);
        }
#pragma unroll
        for (int it = 0; it < 8; it++) {
            int row = lrow + it * 32;
            cp_async16(sb + row * (ROWH * 2), gb + (size_t)row * D_IN);
        }
    };

#pragma unroll
    for (int s = 0; s < STAGES - 1; s++) {
        load_stage(s, s);
        CP_COMMIT();
    }

    float acc[4][8][4];
#pragma unroll
    for (int mi = 0; mi < 4; mi++)
#pragma unroll
        for (int ni = 0; ni < 8; ni++)
#pragma unroll
            for (int c = 0; c < 4; c++) acc[mi][ni][c] = 0.f;

    const int lg = lane >> 3;
    const int lr = lane & 7;
    const int a_row = lr + (lg & 1) * 8;
    const int a_kof = (lg >> 1) * 8;
    const int b_row = lr + (lg >> 1) * 8;
    const int b_kof = (lg & 1) * 8;

    // double-buffered fragments
    uint32_t af[2][4][4];
    uint32_t bf[2][4][4];

    auto load_frag = [&](int buf, uint32_t as_st, uint32_t bs_st, int k0) {
#pragma unroll
        for (int mi = 0; mi < 4; mi++) {
            uint32_t addr = as_st + ((wm + mi * 16 + a_row) * ROWH + k0 + a_kof) * 2;
            LDMATRIX_X4(af[buf][mi][0], af[buf][mi][1], af[buf][mi][2], af[buf][mi][3], addr);
        }
#pragma unroll
        for (int nj = 0; nj < 4; nj++) {
            uint32_t addr = bs_st + ((wn + nj * 16 + b_row) * ROWH + k0 + b_kof) * 2;
            LDMATRIX_X4(bf[buf][nj][0], bf[buf][nj][1], bf[buf][nj][2], bf[buf][nj][3], addr);
        }
    };

    for (int kt = 0; kt < K_ITERS; kt++) {
        CP_WAIT(STAGES - 2);
        __syncthreads();

        if (kt + STAGES - 1 < K_ITERS)
            load_stage(kt + STAGES - 1, (kt + STAGES - 1) % STAGES);
        CP_COMMIT();

        const int s = kt % STAGES;
        const uint32_t as_st = as_base + (s * A_STAGE_H) * 2;
        const uint32_t bs_st = bs_base + (s * B_STAGE_H) * 2;

        load_frag(0, as_st, bs_st, 0);   // prime kk=0

#pragma unroll
        for (int kk = 0; kk < 4; kk++) {
            const int cur = kk & 1;
            if (kk < 3)
                load_frag(cur ^ 1, as_st, bs_st, (kk + 1) * 16);  // prefetch next
#pragma unroll
            for (int mi = 0; mi < 4; mi++)
#pragma unroll
                for (int nj = 0; nj < 4; nj++) {
                    mma_f16(acc[mi][nj * 2 + 0], af[cur][mi], bf[cur][nj][0], bf[cur][nj][1]);
                    mma_f16(acc[mi][nj * 2 + 1], af[cur][mi], bf[cur][nj][2], bf[cur][nj][3]);
                }
        }
    }

    // epilogue
    const int crow = lane >> 2;
    const int ccol = (lane & 3) * 2;
#pragma unroll
    for (int mi = 0; mi < 4; mi++) {
#pragma unroll
        for (int ni = 0; ni < 8; ni++) {
            const size_t m = (size_t)m0 + wm + mi * 16 + crow;
            const int n = n0 + wn + ni * 8 + ccol;
            float2 v0 = {acc[mi][ni][0], acc[mi][ni][1]};
            float2 v1 = {acc[mi][ni][2], acc[mi][ni][3]};
            *reinterpret_cast<float2*>(C + m * D_OUT + n) = v0;
            *reinterpret_cast<float2*>(C + (m + 8) * D_OUT + n) = v1;
        }
    }
}

// ---------------------------------------------------------------------------
// Host side
// ---------------------------------------------------------------------------
extern "C" void kernel_launch(void* const* d_in, const int* in_sizes, int n_in,
                              void* d_out, int out_size) {
    const float* x  = (const float*)d_in[0];
    const int*   q  = (const int*)d_in[1];
    const float* ws = (const float*)d_in[2];
    const float* lA = (const float*)d_in[3];
    const float* lB = (const float*)d_in[4];
    float* out = (float*)d_out;

    __half* wh = nullptr;
    __half* xh = nullptr;
    cudaGetSymbolAddress((void**)&wh, g_wh);
    cudaGetSymbolAddress((void**)&xh, g_xh);

    convert_x_kernel<<<2048, 256>>>((const float4*)x, (uint2*)xh,
                                    (int)((size_t)M_TOT * D_IN / 4));
    dim3 pgrid(D_IN / 64, D_OUT / 64);
    prep_weff_kernel<<<pgrid, 256>>>(q, ws, lA, lB, (uint2*)wh);

    cudaFuncSetAttribute(gemm_f16_kernel,
                         cudaFuncAttributeMaxDynamicSharedMemorySize, SMEM_BYTES);
    gemm_f16_kernel<<<M_TILES * N_TILES, 256, SMEM_BYTES>>>(xh, wh, out);
}

// round 6
// speedup vs baseline: 1.0989x; 1.0989x over previous
#include <cuda_runtime.h>
#include <cuda_fp16.h>
#include <cstdint>

// ---------------------------------------------------------------------------
// Problem constants
// ---------------------------------------------------------------------------
#define D_IN   4096
#define D_OUT  4096
#define M_TOT  8192
#define RANK   64

// GEMM tiling (fp16 operands, fp32 accumulate)
#define TM 128
#define TN 128
#define TK 64                        // halves per K-stage = 128 bytes
#define STAGES 3
#define K_ITERS (D_IN / TK)          // 64
#define M_TILES (M_TOT / TM)         // 64
#define N_TILES (D_OUT / TN)         // 32

#define PADH 8
#define ROWH (TK + PADH)             // 72 halves = 144 B rows
#define A_STAGE_H (TM * ROWH)
#define B_STAGE_H (TN * ROWH)
#define SMEM_BYTES ((STAGES * (A_STAGE_H + B_STAGE_H)) * 2)   // 110592 -> 2 CTAs/SM

// ---------------------------------------------------------------------------
// Device globals (allocation-free scratch)
// ---------------------------------------------------------------------------
__constant__ float c_nf4[16] = {
    -1.0f, -0.6962f, -0.5251f, -0.3949f, -0.2844f, -0.1848f,
    -0.0911f, 0.0f, 0.0796f, 0.1609f, 0.2461f, 0.3379f,
    0.4407f, 0.5626f, 0.723f, 1.0f};

__device__ __align__(1024) __half g_wh[(size_t)D_OUT * D_IN];
__device__ __align__(1024) __half g_xh[(size_t)M_TOT * D_IN];

// ---------------------------------------------------------------------------
// Helpers
// ---------------------------------------------------------------------------
__device__ __forceinline__ void cp_async16(uint32_t smem_addr, const void* gptr) {
    asm volatile("cp.async.cg.shared.global [%0], [%1], 16;"
                 :: "r"(smem_addr), "l"(gptr) : "memory");
}
#define CP_COMMIT() asm volatile("cp.async.commit_group;" ::: "memory")
#define CP_WAIT(n)  asm volatile("cp.async.wait_group %0;" :: "n"(n) : "memory")

#define LDMATRIX_X4(r0, r1, r2, r3, addr)                                     \
    asm volatile("ldmatrix.sync.aligned.m8n8.x4.shared.b16 {%0,%1,%2,%3}, [%4];" \
                 : "=r"(r0), "=r"(r1), "=r"(r2), "=r"(r3) : "r"(addr))

__device__ __forceinline__ void mma_f16(float* c, const uint32_t* a,
                                        uint32_t b0, uint32_t b1) {
    asm volatile(
        "mma.sync.aligned.m16n8k16.row.col.f32.f16.f16.f32 "
        "{%0,%1,%2,%3}, {%4,%5,%6,%7}, {%8,%9}, {%0,%1,%2,%3};"
        : "+f"(c[0]), "+f"(c[1]), "+f"(c[2]), "+f"(c[3])
        : "r"(a[0]), "r"(a[1]), "r"(a[2]), "r"(a[3]), "r"(b0), "r"(b1));
}

__device__ __forceinline__ uint32_t h2_bits(__half2 h) {
    return *reinterpret_cast<uint32_t*>(&h);
}

// ---------------------------------------------------------------------------
// Prep 1: convert x to fp16
// ---------------------------------------------------------------------------
__global__ __launch_bounds__(256) void convert_x_kernel(const float4* __restrict__ x,
                                                        uint2* __restrict__ xh, int n4) {
    int i = blockIdx.x * blockDim.x + threadIdx.x;
    int stride = gridDim.x * blockDim.x;
    for (; i < n4; i += stride) {
        float4 v = x[i];
        uint2 o;
        o.x = h2_bits(__floats2half2_rn(v.x, v.y));
        o.y = h2_bits(__floats2half2_rn(v.z, v.w));
        xh[i] = o;
    }
}

// ---------------------------------------------------------------------------
// Prep 2: W_eff[o,i] = NF4[q[o,i]]*scale + 0.25 * (B@A)[o,i], to fp16
// ---------------------------------------------------------------------------
__global__ __launch_bounds__(256) void prep_weff_kernel(
    const int* __restrict__ q, const float* __restrict__ wscale,
    const float* __restrict__ lA, const float* __restrict__ lB,
    uint2* __restrict__ wh) {
    __shared__ float sA[64][68];
    __shared__ float sB[64][68];
    const int tid = threadIdx.x;
    const int i0 = blockIdx.x * 64;
    const int o0 = blockIdx.y * 64;

    for (int idx = tid; idx < 64 * 64; idx += 256) {
        int r = idx >> 6, c = idx & 63;
        sA[r][c] = lA[r * D_IN + i0 + c];
    }
    for (int idx = tid; idx < 64 * 64; idx += 256) {
        int o = idx >> 6, r = idx & 63;
        sB[r][o] = lB[(size_t)(o0 + o) * RANK + r];
    }
    __syncthreads();

    const int tx = tid & 15;
    const int ty = tid >> 4;
    float acc[4][4] = {};
#pragma unroll
    for (int r = 0; r < 64; r++) {
        const float4 av = *reinterpret_cast<const float4*>(&sA[r][tx * 4]);
        const float4 bv = *reinterpret_cast<const float4*>(&sB[r][ty * 4]);
        const float a[4] = {av.x, av.y, av.z, av.w};
        const float b[4] = {bv.x, bv.y, bv.z, bv.w};
#pragma unroll
        for (int ii = 0; ii < 4; ii++)
#pragma unroll
            for (int jj = 0; jj < 4; jj++)
                acc[ii][jj] += b[ii] * a[jj];
    }

    const float s = wscale[0];
#pragma unroll
    for (int ii = 0; ii < 4; ii++) {
        const size_t o = o0 + ty * 4 + ii;
        const int4 qv = *reinterpret_cast<const int4*>(&q[o * D_IN + i0 + tx * 4]);
        float f0 = c_nf4[qv.x & 15] * s + 0.25f * acc[ii][0];
        float f1 = c_nf4[qv.y & 15] * s + 0.25f * acc[ii][1];
        float f2 = c_nf4[qv.z & 15] * s + 0.25f * acc[ii][2];
        float f3 = c_nf4[qv.w & 15] * s + 0.25f * acc[ii][3];
        uint2 o2;
        o2.x = h2_bits(__floats2half2_rn(f0, f1));
        o2.y = h2_bits(__floats2half2_rn(f2, f3));
        wh[(o * D_IN + i0 + tx * 4) >> 2] = o2;
    }
}

// ---------------------------------------------------------------------------
// Main GEMM: C[m,n] = sum_k Xh[m,k] * Wh[n,k]
// 128x128 CTA tile, 128 threads (4 warps, 2x2 of 64x64 warp tiles),
// 3-stage cp.async, 2 CTAs/SM for cross-CTA latency hiding.
// ---------------------------------------------------------------------------
__global__ void __launch_bounds__(128, 2)
gemm_f16_kernel(const __half* __restrict__ A, const __half* __restrict__ B,
                float* __restrict__ C) {
    extern __shared__ __half smem[];
    __half* As = smem;
    __half* Bs = smem + STAGES * A_STAGE_H;

    const int tid = threadIdx.x;
    const int warp = tid >> 5;
    const int lane = tid & 31;

    const int bid = blockIdx.x;
    const int GROUP_M = 8;
    const int per_group = GROUP_M * N_TILES;
    const int g = bid / per_group, rem = bid % per_group;
    const int mt = g * GROUP_M + (rem % GROUP_M);
    const int nt = rem / GROUP_M;
    const int m0 = mt * TM, n0 = nt * TN;

    // 2x2 warp grid, 64x64 warp tiles
    const int wm = (warp & 1) * 64;
    const int wn = (warp >> 1) * 64;

    // cp.async: 8 threads per 128B row -> 16 rows per pass with 128 threads
    const int lrow = tid >> 3;                    // 0..15
    const int lcolh = (tid & 7) * 8;              // half col 0..56

    const uint32_t as_base = (uint32_t)__cvta_generic_to_shared(As);
    const uint32_t bs_base = (uint32_t)__cvta_generic_to_shared(Bs);

    auto load_stage = [&](int kt, int s) {
        const int k0 = kt * TK;
        const __half* ga = A + (size_t)m0 * D_IN + k0 + lcolh;
        const __half* gb = B + (size_t)n0 * D_IN + k0 + lcolh;
        uint32_t sa = as_base + (s * A_STAGE_H + lcolh) * 2;
        uint32_t sb = bs_base + (s * B_STAGE_H + lcolh) * 2;
#pragma unroll
        for (int it = 0; it < 8; it++) {            // 128 A rows
            int row = lrow + it * 16;
            cp_async16(sa + row * (ROWH * 2), ga + (size_t)row * D_IN);
        }
#pragma unroll
        for (int it = 0; it < 8; it++) {            // 128 B rows
            int row = lrow + it * 16;
            cp_async16(sb + row * (ROWH * 2), gb + (size_t)row * D_IN);
        }
    };

#pragma unroll
    for (int s = 0; s < STAGES - 1; s++) {
        load_stage(s, s);
        CP_COMMIT();
    }

    float acc[4][8][4];
#pragma unroll
    for (int mi = 0; mi < 4; mi++)
#pragma unroll
        for (int ni = 0; ni < 8; ni++)
#pragma unroll
            for (int c = 0; c < 4; c++) acc[mi][ni][c] = 0.f;

    const int lg = lane >> 3;
    const int lr = lane & 7;
    const int a_row = lr + (lg & 1) * 8;
    const int a_kof = (lg >> 1) * 8;
    const int b_row = lr + (lg >> 1) * 8;
    const int b_kof = (lg & 1) * 8;

    uint32_t af[2][4][4];
    uint32_t bf[2][4][4];

    auto load_frag = [&](int buf, uint32_t as_st, uint32_t bs_st, int k0) {
#pragma unroll
        for (int mi = 0; mi < 4; mi++) {
            uint32_t addr = as_st + ((wm + mi * 16 + a_row) * ROWH + k0 + a_kof) * 2;
            LDMATRIX_X4(af[buf][mi][0], af[buf][mi][1], af[buf][mi][2], af[buf][mi][3], addr);
        }
#pragma unroll
        for (int nj = 0; nj < 4; nj++) {
            uint32_t addr = bs_st + ((wn + nj * 16 + b_row) * ROWH + k0 + b_kof) * 2;
            LDMATRIX_X4(bf[buf][nj][0], bf[buf][nj][1], bf[buf][nj][2], bf[buf][nj][3], addr);
        }
    };

    for (int kt = 0; kt < K_ITERS; kt++) {
        CP_WAIT(STAGES - 2);
        __syncthreads();

        if (kt + STAGES - 1 < K_ITERS)
            load_stage(kt + STAGES - 1, (kt + STAGES - 1) % STAGES);
        CP_COMMIT();

        const int s = kt % STAGES;
        const uint32_t as_st = as_base + (s * A_STAGE_H) * 2;
        const uint32_t bs_st = bs_base + (s * B_STAGE_H) * 2;

        load_frag(0, as_st, bs_st, 0);

#pragma unroll
        for (int kk = 0; kk < 4; kk++) {
            const int cur = kk & 1;
            if (kk < 3)
                load_frag(cur ^ 1, as_st, bs_st, (kk + 1) * 16);
#pragma unroll
            for (int mi = 0; mi < 4; mi++)
#pragma unroll
                for (int nj = 0; nj < 4; nj++) {
                    mma_f16(acc[mi][nj * 2 + 0], af[cur][mi], bf[cur][nj][0], bf[cur][nj][1]);
                    mma_f16(acc[mi][nj * 2 + 1], af[cur][mi], bf[cur][nj][2], bf[cur][nj][3]);
                }
        }
    }

    // epilogue
    const int crow = lane >> 2;
    const int ccol = (lane & 3) * 2;
#pragma unroll
    for (int mi = 0; mi < 4; mi++) {
#pragma unroll
        for (int ni = 0; ni < 8; ni++) {
            const size_t m = (size_t)m0 + wm + mi * 16 + crow;
            const int n = n0 + wn + ni * 8 + ccol;
            float2 v0 = {acc[mi][ni][0], acc[mi][ni][1]};
            float2 v1 = {acc[mi][ni][2], acc[mi][ni][3]};
            *reinterpret_cast<float2*>(C + m * D_OUT + n) = v0;
            *reinterpret_cast<float2*>(C + (m + 8) * D_OUT + n) = v1;
        }
    }
}

// ---------------------------------------------------------------------------
// Host side
// ---------------------------------------------------------------------------
extern "C" void kernel_launch(void* const* d_in, const int* in_sizes, int n_in,
                              void* d_out, int out_size) {
    const float* x  = (const float*)d_in[0];
    const int*   q  = (const int*)d_in[1];
    const float* ws = (const float*)d_in[2];
    const float* lA = (const float*)d_in[3];
    const float* lB = (const float*)d_in[4];
    float* out = (float*)d_out;

    __half* wh = nullptr;
    __half* xh = nullptr;
    cudaGetSymbolAddress((void**)&wh, g_wh);
    cudaGetSymbolAddress((void**)&xh, g_xh);

    convert_x_kernel<<<2048, 256>>>((const float4*)x, (uint2*)xh,
                                    (int)((size_t)M_TOT * D_IN / 4));
    dim3 pgrid(D_IN / 64, D_OUT / 64);
    prep_weff_kernel<<<pgrid, 256>>>(q, ws, lA, lB, (uint2*)wh);

    cudaFuncSetAttribute(gemm_f16_kernel,
                         cudaFuncAttributeMaxDynamicSharedMemorySize, SMEM_BYTES);
    gemm_f16_kernel<<<M_TILES * N_TILES, 128, SMEM_BYTES>>>(xh, wh, out);
}

// round 8
// speedup vs baseline: 1.3750x; 1.2512x over previous
#include <cuda_runtime.h>
#include <cuda.h>
#include <cuda_fp16.h>
#include <cstdint>

// ---------------------------------------------------------------------------
// Problem constants
// ---------------------------------------------------------------------------
#define D_IN   4096
#define D_OUT  4096
#define M_TOT  8192
#define RANK   64

// GEMM tiling (fp16 operands, fp32 accumulate)
#define TM 128
#define TN 128
#define TK 64                        // halves per K-stage = 128 B (one SW128 row)
#define STAGES 3
#define K_ITERS (D_IN / TK)          // 64
#define M_TILES (M_TOT / TM)         // 64
#define N_TILES (D_OUT / TN)         // 32

#define A_STAGE_B (TM * 128)         // 16384 bytes
#define B_STAGE_B (TN * 128)         // 16384 bytes
#define SMEM_FULL(s)  ((s) * 8)
#define SMEM_A_OFF    1024
#define SMEM_B_OFF    (SMEM_A_OFF + STAGES * A_STAGE_B)     // 50176
#define SMEM_BYTES    (SMEM_B_OFF + STAGES * B_STAGE_B)     // 99328 -> 2 CTAs/SM

// ---------------------------------------------------------------------------
// Device globals (allocation-free scratch)
// ---------------------------------------------------------------------------
__constant__ float c_nf4[16] = {
    -1.0f, -0.6962f, -0.5251f, -0.3949f, -0.2844f, -0.1848f,
    -0.0911f, 0.0f, 0.0796f, 0.1609f, 0.2461f, 0.3379f,
    0.4407f, 0.5626f, 0.723f, 1.0f};

__device__ __align__(1024) __half g_wh[(size_t)D_OUT * D_IN];
__device__ __align__(1024) __half g_xh[(size_t)M_TOT * D_IN];

// ---------------------------------------------------------------------------
// PTX helpers
// ---------------------------------------------------------------------------
#define LDMATRIX_X4(r0, r1, r2, r3, addr)                                     \
    asm volatile("ldmatrix.sync.aligned.m8n8.x4.shared.b16 {%0,%1,%2,%3}, [%4];" \
                 : "=r"(r0), "=r"(r1), "=r"(r2), "=r"(r3) : "r"(addr))

__device__ __forceinline__ void mma_f16(float* c, const uint32_t* a,
                                        uint32_t b0, uint32_t b1) {
    asm volatile(
        "mma.sync.aligned.m16n8k16.row.col.f32.f16.f16.f32 "
        "{%0,%1,%2,%3}, {%4,%5,%6,%7}, {%8,%9}, {%0,%1,%2,%3};"
        : "+f"(c[0]), "+f"(c[1]), "+f"(c[2]), "+f"(c[3])
        : "r"(a[0]), "r"(a[1]), "r"(a[2]), "r"(a[3]), "r"(b0), "r"(b1));
}

#define MBAR_INIT(addr, cnt) \
    asm volatile("mbarrier.init.shared.b64 [%0], %1;" :: "r"(addr), "r"(cnt) : "memory")

#define MBAR_EXPECT_TX(addr, bytes) \
    asm volatile("mbarrier.arrive.expect_tx.shared.b64 _, [%0], %1;" \
                 :: "r"(addr), "r"(bytes) : "memory")

#define MBAR_WAIT(addr, ph) do {                                                  \
    uint32_t _d = 0;                                                              \
    do {                                                                          \
        asm volatile("{\n\t.reg .pred P;\n\t"                                     \
            "mbarrier.try_wait.parity.acquire.cta.shared::cta.b64 P, [%1], %2, 0x989680;\n\t" \
            "selp.b32 %0, 1, 0, P;\n\t}"                                          \
            : "=r"(_d) : "r"(addr), "r"(ph) : "memory");                          \
    } while (!_d);                                                                \
} while (0)

#define TMA_LOAD_2D(smem_addr, tmap, cx, cy, mbar) \
    asm volatile( \
        "cp.async.bulk.tensor.2d.shared::cta.global.tile.mbarrier::complete_tx::bytes " \
        "[%0], [%1, {%2, %3}], [%4];" \
        :: "r"(smem_addr), "l"(tmap), "r"(cx), "r"(cy), "r"(mbar) : "memory")

__device__ __forceinline__ uint32_t h2_bits(__half2 h) {
    return *reinterpret_cast<uint32_t*>(&h);
}

// ---------------------------------------------------------------------------
// Prep 1: convert x to fp16
// ---------------------------------------------------------------------------
__global__ __launch_bounds__(256) void convert_x_kernel(const float4* __restrict__ x,
                                                        uint2* __restrict__ xh, int n4) {
    int i = blockIdx.x * blockDim.x + threadIdx.x;
    int stride = gridDim.x * blockDim.x;
    for (; i < n4; i += stride) {
        float4 v = x[i];
        uint2 o;
        o.x = h2_bits(__floats2half2_rn(v.x, v.y));
        o.y = h2_bits(__floats2half2_rn(v.z, v.w));
        xh[i] = o;
    }
}

// ---------------------------------------------------------------------------
// Prep 2: W_eff[o,i] = NF4[q[o,i]]*scale + 0.25 * (B@A)[o,i], to fp16
// ---------------------------------------------------------------------------
__global__ __launch_bounds__(256) void prep_weff_kernel(
    const int* __restrict__ q, const float* __restrict__ wscale,
    const float* __restrict__ lA, const float* __restrict__ lB,
    uint2* __restrict__ wh) {
    __shared__ float sA[64][68];
    __shared__ float sB[64][68];
    const int tid = threadIdx.x;
    const int i0 = blockIdx.x * 64;
    const int o0 = blockIdx.y * 64;

    for (int idx = tid; idx < 64 * 64; idx += 256) {
        int r = idx >> 6, c = idx & 63;
        sA[r][c] = lA[r * D_IN + i0 + c];
    }
    for (int idx = tid; idx < 64 * 64; idx += 256) {
        int o = idx >> 6, r = idx & 63;
        sB[r][o] = lB[(size_t)(o0 + o) * RANK + r];
    }
    __syncthreads();

    const int tx = tid & 15;
    const int ty = tid >> 4;
    float acc[4][4] = {};
#pragma unroll
    for (int r = 0; r < 64; r++) {
        const float4 av = *reinterpret_cast<const float4*>(&sA[r][tx * 4]);
        const float4 bv = *reinterpret_cast<const float4*>(&sB[r][ty * 4]);
        const float a[4] = {av.x, av.y, av.z, av.w};
        const float b[4] = {bv.x, bv.y, bv.z, bv.w};
#pragma unroll
        for (int ii = 0; ii < 4; ii++)
#pragma unroll
            for (int jj = 0; jj < 4; jj++)
                acc[ii][jj] += b[ii] * a[jj];
    }

    const float s = wscale[0];
#pragma unroll
    for (int ii = 0; ii < 4; ii++) {
        const size_t o = o0 + ty * 4 + ii;
        const int4 qv = *reinterpret_cast<const int4*>(&q[o * D_IN + i0 + tx * 4]);
        float f0 = c_nf4[qv.x & 15] * s + 0.25f * acc[ii][0];
        float f1 = c_nf4[qv.y & 15] * s + 0.25f * acc[ii][1];
        float f2 = c_nf4[qv.z & 15] * s + 0.25f * acc[ii][2];
        float f3 = c_nf4[qv.w & 15] * s + 0.25f * acc[ii][3];
        uint2 o2;
        o2.x = h2_bits(__floats2half2_rn(f0, f1));
        o2.y = h2_bits(__floats2half2_rn(f2, f3));
        wh[(o * D_IN + i0 + tx * 4) >> 2] = o2;
    }
}

// ---------------------------------------------------------------------------
// Main GEMM: C[m,n] = sum_k Xh[m,k] * Wh[n,k]
// 128x128 CTA, 4 warps (64x64 tiles), TMA + full-mbarriers, stage release via
// __syncthreads (proven R4-R6 discipline); 2 CTAs/SM.
// ---------------------------------------------------------------------------
__global__ void __launch_bounds__(128, 2)
gemm_f16_kernel(const __grid_constant__ CUtensorMap tma_a,
                const __grid_constant__ CUtensorMap tma_b,
                float* __restrict__ C) {
    extern __shared__ char smem[];
    const uint32_t sb = (uint32_t)__cvta_generic_to_shared(smem);

    const int tid = threadIdx.x;
    const int warp = tid >> 5;
    const int lane = tid & 31;

    const int bid = blockIdx.x;
    const int GROUP_M = 8;
    const int per_group = GROUP_M * N_TILES;
    const int g = bid / per_group, rem = bid % per_group;
    const int mt = g * GROUP_M + (rem % GROUP_M);
    const int nt = rem / GROUP_M;
    const int m0 = mt * TM, n0 = nt * TN;

    const int wm = (warp & 1) * 64;
    const int wn = (warp >> 1) * 64;

    if (tid == 0) {
        for (int s = 0; s < STAGES; s++)
            MBAR_INIT(sb + SMEM_FULL(s), 1);
        asm volatile("fence.proxy.async.shared::cta;" ::: "memory");
    }
    __syncthreads();

    // prologue: load all STAGES stages
    if (tid == 0) {
#pragma unroll
        for (int s = 0; s < STAGES; s++) {
            MBAR_EXPECT_TX(sb + SMEM_FULL(s), A_STAGE_B + B_STAGE_B);
            TMA_LOAD_2D(sb + SMEM_A_OFF + s * A_STAGE_B, &tma_a, s * TK, m0,
                        sb + SMEM_FULL(s));
            TMA_LOAD_2D(sb + SMEM_B_OFF + s * B_STAGE_B, &tma_b, s * TK, n0,
                        sb + SMEM_FULL(s));
        }
    }

    float acc[4][8][4];
#pragma unroll
    for (int mi = 0; mi < 4; mi++)
#pragma unroll
        for (int ni = 0; ni < 8; ni++)
#pragma unroll
            for (int c = 0; c < 4; c++) acc[mi][ni][c] = 0.f;

    // ldmatrix lane addressing (SW128 swizzle: 16B chunk ^= row & 7)
    const int lg = lane >> 3;
    const int lr = lane & 7;
    const int a_row = lr + (lg & 1) * 8;
    const int a_kch = lg >> 1;
    const int b_row = lr + (lg >> 1) * 8;
    const int b_kch = lg & 1;

    uint32_t af[2][4][4];
    uint32_t bf[2][4][4];

    auto load_frag = [&](int buf, uint32_t a_st, uint32_t b_st, int kk) {
#pragma unroll
        for (int mi = 0; mi < 4; mi++) {
            const int row = wm + mi * 16 + a_row;
            const int ch = (2 * kk + a_kch) ^ (row & 7);
            uint32_t addr = a_st + row * 128 + ch * 16;
            LDMATRIX_X4(af[buf][mi][0], af[buf][mi][1], af[buf][mi][2], af[buf][mi][3], addr);
        }
#pragma unroll
        for (int nj = 0; nj < 4; nj++) {
            const int row = wn + nj * 16 + b_row;
            const int ch = (2 * kk + b_kch) ^ (row & 7);
            uint32_t addr = b_st + row * 128 + ch * 16;
            LDMATRIX_X4(bf[buf][nj][0], bf[buf][nj][1], bf[buf][nj][2], bf[buf][nj][3], addr);
        }
    };

    int cs = 0, cph = 0;

    for (int kt = 0; kt < K_ITERS; kt++) {
        // wait for stage kt's data
        MBAR_WAIT(sb + SMEM_FULL(cs), cph);

        const uint32_t a_st = sb + SMEM_A_OFF + cs * A_STAGE_B;
        const uint32_t b_st = sb + SMEM_B_OFF + cs * B_STAGE_B;

        load_frag(0, a_st, b_st, 0);
#pragma unroll
        for (int kk = 0; kk < 4; kk++) {
            const int cur = kk & 1;
            if (kk < 3)
                load_frag(cur ^ 1, a_st, b_st, kk + 1);
#pragma unroll
            for (int mi = 0; mi < 4; mi++)
#pragma unroll
                for (int nj = 0; nj < 4; nj++) {
                    mma_f16(acc[mi][nj * 2 + 0], af[cur][mi], bf[cur][nj][0], bf[cur][nj][1]);
                    mma_f16(acc[mi][nj * 2 + 1], af[cur][mi], bf[cur][nj][2], bf[cur][nj][3]);
                }
        }

        // stage release: everyone done reading slot cs
        __syncthreads();

        // refill slot cs with k-iter kt+STAGES
        if (tid == 0 && kt + STAGES < K_ITERS) {
            const int li = kt + STAGES;
            MBAR_EXPECT_TX(sb + SMEM_FULL(cs), A_STAGE_B + B_STAGE_B);
            TMA_LOAD_2D(sb + SMEM_A_OFF + cs * A_STAGE_B, &tma_a, li * TK, m0,
                        sb + SMEM_FULL(cs));
            TMA_LOAD_2D(sb + SMEM_B_OFF + cs * B_STAGE_B, &tma_b, li * TK, n0,
                        sb + SMEM_FULL(cs));
        }

        if (++cs == STAGES) { cs = 0; cph ^= 1; }
    }

    // epilogue
    const int crow = lane >> 2;
    const int ccol = (lane & 3) * 2;
#pragma unroll
    for (int mi = 0; mi < 4; mi++) {
#pragma unroll
        for (int ni = 0; ni < 8; ni++) {
            const size_t m = (size_t)m0 + wm + mi * 16 + crow;
            const int n = n0 + wn + ni * 8 + ccol;
            float2 v0 = {acc[mi][ni][0], acc[mi][ni][1]};
            float2 v1 = {acc[mi][ni][2], acc[mi][ni][3]};
            *reinterpret_cast<float2*>(C + m * D_OUT + n) = v0;
            *reinterpret_cast<float2*>(C + (m + 8) * D_OUT + n) = v1;
        }
    }
}

// ---------------------------------------------------------------------------
// Host side
// ---------------------------------------------------------------------------
typedef CUresult (*EncodeFn)(CUtensorMap*, CUtensorMapDataType, cuuint32_t, void*,
                             const cuuint64_t*, const cuuint64_t*, const cuuint32_t*,
                             const cuuint32_t*, CUtensorMapInterleave, CUtensorMapSwizzle,
                             CUtensorMapL2promotion, CUtensorMapFloatOOBfill);

static EncodeFn get_encode_fn() {
    void* fn = nullptr;
    cudaDriverEntryPointQueryResult st;
#if CUDART_VERSION >= 12050
    cudaGetDriverEntryPointByVersion("cuTensorMapEncodeTiled", &fn, 12000,
                                     cudaEnableDefault, &st);
#else
    cudaGetDriverEntryPoint("cuTensorMapEncodeTiled", &fn, cudaEnableDefault, &st);
#endif
    return (EncodeFn)fn;
}

static void encode_2d_f16(EncodeFn fn, CUtensorMap* tm, void* ptr,
                          uint64_t dim0, uint64_t dim1, uint32_t box0, uint32_t box1) {
    cuuint64_t dims[2] = {dim0, dim1};
    cuuint64_t strides[1] = {dim0 * 2};
    cuuint32_t box[2] = {box0, box1};
    cuuint32_t es[2] = {1, 1};
    fn(tm, CU_TENSOR_MAP_DATA_TYPE_FLOAT16, 2, ptr, dims, strides, box, es,
       CU_TENSOR_MAP_INTERLEAVE_NONE, CU_TENSOR_MAP_SWIZZLE_128B,
       CU_TENSOR_MAP_L2_PROMOTION_L2_128B, CU_TENSOR_MAP_FLOAT_OOB_FILL_NONE);
}

extern "C" void kernel_launch(void* const* d_in, const int* in_sizes, int n_in,
                              void* d_out, int out_size) {
    const float* x  = (const float*)d_in[0];
    const int*   q  = (const int*)d_in[1];
    const float* ws = (const float*)d_in[2];
    const float* lA = (const float*)d_in[3];
    const float* lB = (const float*)d_in[4];
    float* out = (float*)d_out;

    __half* wh = nullptr;
    __half* xh = nullptr;
    cudaGetSymbolAddress((void**)&wh, g_wh);
    cudaGetSymbolAddress((void**)&xh, g_xh);

    convert_x_kernel<<<2048, 256>>>((const float4*)x, (uint2*)xh,
                                    (int)((size_t)M_TOT * D_IN / 4));
    dim3 pgrid(D_IN / 64, D_OUT / 64);
    prep_weff_kernel<<<pgrid, 256>>>(q, ws, lA, lB, (uint2*)wh);

    EncodeFn enc = get_encode_fn();
    CUtensorMap tm_a, tm_b;
    encode_2d_f16(enc, &tm_a, xh, D_IN, M_TOT, TK, TM);
    encode_2d_f16(enc, &tm_b, wh, D_IN, D_OUT, TK, TN);

    cudaFuncSetAttribute(gemm_f16_kernel,
                         cudaFuncAttributeMaxDynamicSharedMemorySize, SMEM_BYTES);
    gemm_f16_kernel<<<M_TILES * N_TILES, 128, SMEM_BYTES>>>(tm_a, tm_b, out);
}